// round 8
// baseline (speedup 1.0000x reference)
#include <cuda_runtime.h>
#include <cuda_bf16.h>
#include <cstdint>

#define L_   512
#define B_   128
#define D_   128
#define H_   512
#define OUT_ 5
#define M_   (L_*B_)     // 65536 rows
#define N3_  (3*H_)      // 1536 cols

// ---------------------------------------------------------------------------
// Static device scratch (no cudaMalloc allowed)
// ---------------------------------------------------------------------------
__device__ float         g_U   [(size_t)M_ * N3_];          // 402 MB
__device__ __nv_bfloat16 g_Ahi [(size_t)M_ * H_];           // 64 MB (x split / h1 hi)
__device__ __nv_bfloat16 g_Alo [(size_t)M_ * H_];           // 64 MB (x split / h1 lo)
__device__ __nv_bfloat16 g_BtHi[(size_t)N3_ * H_];          // 1.5 MB
__device__ __nv_bfloat16 g_BtLo[(size_t)N3_ * H_];
__device__ float         g_h2  [B_ * H_];

// ---------------------------------------------------------------------------
// Helpers (base-ISA only: ldmatrix / mma.sync / cp.async — no 'a' features)
// ---------------------------------------------------------------------------
__device__ __forceinline__ uint32_t smem_to_u32(const void* p) {
    uint32_t a;
    asm("{ .reg .u64 t; cvta.to.shared.u64 t, %1; cvt.u32.u64 %0, t; }" : "=r"(a) : "l"(p));
    return a;
}
#define SW128(bo) ((bo) ^ (((bo) >> 3) & 0x70))

__device__ __forceinline__ void cp_async16(uint32_t dst, const void* src) {
    asm volatile("cp.async.cg.shared.global [%0], [%1], 16;" :: "r"(dst), "l"(src) : "memory");
}
__device__ __forceinline__ void cp_commit() {
    asm volatile("cp.async.commit_group;" ::: "memory");
}
template<int N>
__device__ __forceinline__ void cp_wait() {
    asm volatile("cp.async.wait_group %0;" :: "n"(N) : "memory");
}
__device__ __forceinline__ void ldm_x4(uint32_t& r0, uint32_t& r1, uint32_t& r2, uint32_t& r3,
                                       uint32_t addr) {
    asm volatile("ldmatrix.sync.aligned.m8n8.x4.shared.b16 {%0,%1,%2,%3}, [%4];"
                 : "=r"(r0), "=r"(r1), "=r"(r2), "=r"(r3) : "r"(addr));
}
__device__ __forceinline__ void mma_bf16(float* c, const uint32_t* a, const uint32_t* b) {
    asm volatile(
        "mma.sync.aligned.m16n8k16.row.col.f32.bf16.bf16.f32 "
        "{%0,%1,%2,%3}, {%4,%5,%6,%7}, {%8,%9}, {%0,%1,%2,%3};"
        : "+f"(c[0]), "+f"(c[1]), "+f"(c[2]), "+f"(c[3])
        : "r"(a[0]), "r"(a[1]), "r"(a[2]), "r"(a[3]), "r"(b[0]), "r"(b[1]));
}
__device__ __forceinline__ void stcs2(float* p, float x, float y) {
    asm volatile("st.global.cs.v2.f32 [%0], {%1, %2};" :: "l"(p), "f"(x), "f"(y) : "memory");
}

// ---------------------------------------------------------------------------
// GEMM: C[M x N3] = (Ahi+Alo)[M x K] @ (Bhi+Blo)^T[N3 x K], fp32-via-3xbf16.
// CTA tile 128x256, BK=64, 8 warps (2m x 4n), warp tile 64x64.
// SMEM/stage: Ahi|Alo (16KB each) + Bhi|Blo (32KB each) = 96KB, 2 stages.
// Products staged hi*hi -> hi*lo -> lo*hi to bound register pressure.
// ---------------------------------------------------------------------------
#define OFF_AHI  0
#define OFF_ALO  16384
#define OFF_BHI  32768
#define OFF_BLO  65536
#define STAGE_B  98304                 // 96 KB
#define GEMM_SMEM (2*STAGE_B)          // 192 KB

template<int KTOT>
__device__ __forceinline__ void load_stage(uint32_t sb, int buf, int kt,
    const __nv_bfloat16* __restrict__ Ahi, const __nv_bfloat16* __restrict__ Alo,
    const __nv_bfloat16* __restrict__ Bhi, const __nv_bfloat16* __restrict__ Blo,
    int rowBase, int colBase, int tid)
{
    const uint32_t base = sb + buf * STAGE_B;
    const int kOff = kt * 64;
    #pragma unroll
    for (int i = 0; i < 4; i++) {                 // A: 128 rows x 128B, hi+lo
        const int ci = tid + i * 256;
        const int row = ci >> 3, c8 = ci & 7;
        const size_t g = (size_t)(rowBase + row) * KTOT + kOff + c8 * 8;
        const uint32_t so = SW128((uint32_t)(row * 128 + c8 * 16));
        cp_async16(base + OFF_AHI + so, Ahi + g);
        cp_async16(base + OFF_ALO + so, Alo + g);
    }
    #pragma unroll
    for (int i = 0; i < 8; i++) {                 // B: 256 rows x 128B, hi+lo
        const int ci = tid + i * 256;
        const int row = ci >> 3, c8 = ci & 7;
        const size_t g = (size_t)(colBase + row) * KTOT + kOff + c8 * 8;
        const uint32_t so = SW128((uint32_t)(row * 128 + c8 * 16));
        cp_async16(base + OFF_BHI + so, Bhi + g);
        cp_async16(base + OFF_BLO + so, Blo + g);
    }
}

__device__ __forceinline__ void compute_stage(uint32_t sb, int buf,
    int warp_m, int warp_n, int lane, float acc[4][8][4])
{
    const uint32_t base = sb + buf * STAGE_B;
    const int mrow = warp_m * 64 + (lane & 15);
    const int bg = lane >> 3, brr = lane & 7;
    #pragma unroll
    for (int k16 = 0; k16 < 4; k16++) {
        const int kc = k16 * 2 + (lane >> 4);
        uint32_t af[4][4];   // A fragments (reused for hi then lo)
        uint32_t bhi[8][2];  // B hi fragments (live across all 3 products)
        uint32_t bx[8][2];   // B lo fragments (short-lived)

        // --- A hi + B hi ---
        #pragma unroll
        for (int ma = 0; ma < 4; ma++) {
            const uint32_t so = SW128((uint32_t)((mrow + ma * 16) * 128 + kc * 16));
            ldm_x4(af[ma][0], af[ma][1], af[ma][2], af[ma][3], base + OFF_AHI + so);
        }
        #pragma unroll
        for (int ng = 0; ng < 4; ng++) {
            const int n = warp_n * 64 + ng * 16 + (bg >> 1) * 8 + brr;
            const uint32_t so = SW128((uint32_t)(n * 128 + (k16 * 2 + (bg & 1)) * 16));
            uint32_t r0, r1, r2, r3;
            ldm_x4(r0, r1, r2, r3, base + OFF_BHI + so);
            bhi[ng*2][0] = r0; bhi[ng*2][1] = r1; bhi[ng*2+1][0] = r2; bhi[ng*2+1][1] = r3;
        }
        #pragma unroll
        for (int ma = 0; ma < 4; ma++)
            #pragma unroll
            for (int na = 0; na < 8; na++) mma_bf16(acc[ma][na], af[ma], bhi[na]);

        // --- A hi * B lo ---
        #pragma unroll
        for (int ng = 0; ng < 4; ng++) {
            const int n = warp_n * 64 + ng * 16 + (bg >> 1) * 8 + brr;
            const uint32_t so = SW128((uint32_t)(n * 128 + (k16 * 2 + (bg & 1)) * 16));
            uint32_t r0, r1, r2, r3;
            ldm_x4(r0, r1, r2, r3, base + OFF_BLO + so);
            bx[ng*2][0] = r0; bx[ng*2][1] = r1; bx[ng*2+1][0] = r2; bx[ng*2+1][1] = r3;
        }
        #pragma unroll
        for (int ma = 0; ma < 4; ma++)
            #pragma unroll
            for (int na = 0; na < 8; na++) mma_bf16(acc[ma][na], af[ma], bx[na]);

        // --- A lo * B hi ---
        #pragma unroll
        for (int ma = 0; ma < 4; ma++) {
            const uint32_t so = SW128((uint32_t)((mrow + ma * 16) * 128 + kc * 16));
            ldm_x4(af[ma][0], af[ma][1], af[ma][2], af[ma][3], base + OFF_ALO + so);
        }
        #pragma unroll
        for (int ma = 0; ma < 4; ma++)
            #pragma unroll
            for (int na = 0; na < 8; na++) mma_bf16(acc[ma][na], af[ma], bhi[na]);
    }
}

template<int KTOT>
__global__ __launch_bounds__(256, 1)
void gemm_hmma(const __nv_bfloat16* __restrict__ Ahi,
               const __nv_bfloat16* __restrict__ Alo,
               const __nv_bfloat16* __restrict__ Bhi,
               const __nv_bfloat16* __restrict__ Blo,
               float* __restrict__ C)
{
    extern __shared__ char smem[];
    const uint32_t sb = smem_to_u32(smem);
    const int tid = threadIdx.x, wid = tid >> 5, lane = tid & 31;
    const int warp_m = wid & 1, warp_n = wid >> 1;
    const int rowBase = blockIdx.y << 7;
    const int colBase = blockIdx.x << 8;
    constexpr int KT = KTOT / 64;

    float acc[4][8][4];
    #pragma unroll
    for (int i = 0; i < 4; i++)
        #pragma unroll
        for (int j = 0; j < 8; j++)
            #pragma unroll
            for (int k = 0; k < 4; k++) acc[i][j][k] = 0.f;

    load_stage<KTOT>(sb, 0, 0, Ahi, Alo, Bhi, Blo, rowBase, colBase, tid);
    cp_commit();

    #pragma unroll 1
    for (int kt = 0; kt < KT; kt++) {
        if (kt + 1 < KT) {
            load_stage<KTOT>(sb, (kt + 1) & 1, kt + 1, Ahi, Alo, Bhi, Blo,
                             rowBase, colBase, tid);
            cp_commit();
            cp_wait<1>();
        } else {
            cp_wait<0>();
        }
        __syncthreads();
        compute_stage(sb, kt & 1, warp_m, warp_n, lane, acc);
        __syncthreads();
    }

    // Epilogue: streaming fp32 stores (C is written once, read once by rec)
    const int mBase = rowBase + warp_m * 64 + (lane >> 2);
    const int nBase = colBase + warp_n * 64 + (lane & 3) * 2;
    #pragma unroll
    for (int ma = 0; ma < 4; ma++) {
        #pragma unroll
        for (int na = 0; na < 8; na++) {
            const int m = mBase + ma * 16;
            const int n = nBase + na * 8;
            stcs2(C + (size_t)m * N3_ + n,       acc[ma][na][0], acc[ma][na][1]);
            stcs2(C + (size_t)(m + 8) * N3_ + n, acc[ma][na][2], acc[ma][na][3]);
        }
    }
}

// ---------------------------------------------------------------------------
// Split fp32 -> bf16 hi/lo (elementwise, float4-vectorized)
// ---------------------------------------------------------------------------
__global__ void split_kernel(const float* __restrict__ src,
                             __nv_bfloat16* __restrict__ hi,
                             __nv_bfloat16* __restrict__ lo, int n4)
{
    const int i = blockIdx.x * blockDim.x + threadIdx.x;
    if (i >= n4) return;
    const float4 v = reinterpret_cast<const float4*>(src)[i];
    float f[4] = {v.x, v.y, v.z, v.w};
    __nv_bfloat16 h[4], l[4];
    #pragma unroll
    for (int j = 0; j < 4; j++) {
        h[j] = __float2bfloat16(f[j]);
        l[j] = __float2bfloat16(f[j] - __bfloat162float(h[j]));
    }
    __nv_bfloat162* hp = reinterpret_cast<__nv_bfloat162*>(hi + 4 * (size_t)i);
    __nv_bfloat162* lp = reinterpret_cast<__nv_bfloat162*>(lo + 4 * (size_t)i);
    hp[0] = __nv_bfloat162(h[0], h[1]); hp[1] = __nv_bfloat162(h[2], h[3]);
    lp[0] = __nv_bfloat162(l[0], l[1]); lp[1] = __nv_bfloat162(l[2], l[3]);
}

// Transpose + split: W[K, N3] fp32 -> hiT/loT[N3, K] bf16
__global__ void splitT_kernel(const float* __restrict__ W,
                              __nv_bfloat16* __restrict__ hiT,
                              __nv_bfloat16* __restrict__ loT, int K)
{
    const int idx = blockIdx.x * blockDim.x + threadIdx.x;
    if (idx >= K * N3_) return;
    const int k = idx / N3_, n = idx % N3_;
    const float f = W[idx];
    const __nv_bfloat16 h = __float2bfloat16(f);
    hiT[(size_t)n * K + k] = h;
    loT[(size_t)n * K + k] = __float2bfloat16(f - __bfloat162float(h));
}

// ---------------------------------------------------------------------------
// SRU recurrence, prefetch distance 8 (two 4-timestep register batches)
// ---------------------------------------------------------------------------
__device__ __forceinline__ float sigmoidf_(float z) { return 1.f / (1.f + __expf(-z)); }

__global__ __launch_bounds__(256)
void rec0_kernel(const float* __restrict__ U, const float* __restrict__ v,
                 const float* __restrict__ bias,
                 __nv_bfloat16* __restrict__ hHi, __nv_bfloat16* __restrict__ hLo)
{
    const int tid = blockIdx.x * blockDim.x + threadIdx.x;
    const int b = tid >> 9, h = tid & (H_ - 1);
    const float vf = v[h], vr = v[H_ + h];
    const float bf = bias[h], br = bias[H_ + h];
    float c = 0.f;
    float a0[2][4], a1[2][4], a2[2][4];
    #pragma unroll
    for (int s = 0; s < 2; s++)
        #pragma unroll
        for (int i = 0; i < 4; i++) {
            const size_t base = ((size_t)(s * 4 + i) * B_ + b) * N3_ + h;
            a0[s][i] = __ldcs(U + base); a1[s][i] = __ldcs(U + base + H_);
            a2[s][i] = __ldcs(U + base + 2*H_);
        }
    for (int t0 = 0; t0 < L_; t0 += 4) {
        const int cur = (t0 >> 2) & 1;
        float n0[4], n1[4], n2[4];
        const bool pf = (t0 + 8 < L_);
        if (pf) {
            #pragma unroll
            for (int i = 0; i < 4; i++) {
                const size_t base = ((size_t)(t0 + 8 + i) * B_ + b) * N3_ + h;
                n0[i] = __ldcs(U + base); n1[i] = __ldcs(U + base + H_);
                n2[i] = __ldcs(U + base + 2*H_);
            }
        }
        #pragma unroll
        for (int i = 0; i < 4; i++) {
            const float f = sigmoidf_(a1[cur][i] + vf * c + bf);
            const float r = sigmoidf_(a2[cur][i] + vr * c + br);
            c = f * c + (1.f - f) * a0[cur][i];
            const float hv = r * c;
            const __nv_bfloat16 hb = __float2bfloat16(hv);
            const size_t o = ((size_t)(t0 + i) * B_ + b) * H_ + h;
            __stcs(hHi + o, hb);
            __stcs(hLo + o, __float2bfloat16(hv - __bfloat162float(hb)));
        }
        if (pf) {
            #pragma unroll
            for (int i = 0; i < 4; i++) {
                a0[cur][i] = n0[i]; a1[cur][i] = n1[i]; a2[cur][i] = n2[i];
            }
        }
    }
}

__global__ __launch_bounds__(256)
void rec1_kernel(const float* __restrict__ U, const float* __restrict__ v,
                 const float* __restrict__ bias, float* __restrict__ hout)
{
    const int tid = blockIdx.x * blockDim.x + threadIdx.x;
    const int b = tid >> 9, h = tid & (H_ - 1);
    const float vf = v[h], vr = v[H_ + h];
    const float bf = bias[h], br = bias[H_ + h];
    float c = 0.f, hlast = 0.f;
    float a0[2][4], a1[2][4], a2[2][4];
    #pragma unroll
    for (int s = 0; s < 2; s++)
        #pragma unroll
        for (int i = 0; i < 4; i++) {
            const size_t base = ((size_t)(s * 4 + i) * B_ + b) * N3_ + h;
            a0[s][i] = __ldcs(U + base); a1[s][i] = __ldcs(U + base + H_);
            a2[s][i] = __ldcs(U + base + 2*H_);
        }
    for (int t0 = 0; t0 < L_; t0 += 4) {
        const int cur = (t0 >> 2) & 1;
        float n0[4], n1[4], n2[4];
        const bool pf = (t0 + 8 < L_);
        if (pf) {
            #pragma unroll
            for (int i = 0; i < 4; i++) {
                const size_t base = ((size_t)(t0 + 8 + i) * B_ + b) * N3_ + h;
                n0[i] = __ldcs(U + base); n1[i] = __ldcs(U + base + H_);
                n2[i] = __ldcs(U + base + 2*H_);
            }
        }
        #pragma unroll
        for (int i = 0; i < 4; i++) {
            const float f = sigmoidf_(a1[cur][i] + vf * c + bf);
            const float r = sigmoidf_(a2[cur][i] + vr * c + br);
            c = f * c + (1.f - f) * a0[cur][i];
            hlast = r * c;
        }
        if (pf) {
            #pragma unroll
            for (int i = 0; i < 4; i++) {
                a0[cur][i] = n0[i]; a1[cur][i] = n1[i]; a2[cur][i] = n2[i];
            }
        }
    }
    hout[b * H_ + h] = hlast;
}

// ---------------------------------------------------------------------------
// Final FC: out[b,o] = h2[b,:] . fc_w[o,:] + fc_b[o]
// ---------------------------------------------------------------------------
__global__ void fc_kernel(const float* __restrict__ h2, const float* __restrict__ w,
                          const float* __restrict__ bias, float* __restrict__ out)
{
    const int gtid = blockIdx.x * blockDim.x + threadIdx.x;
    const int warp = gtid >> 5, lane = gtid & 31;
    if (warp >= B_) return;
    #pragma unroll
    for (int o = 0; o < OUT_; o++) {
        float s = 0.f;
        for (int h = lane; h < H_; h += 32) s += h2[warp * H_ + h] * w[o * H_ + h];
        #pragma unroll
        for (int off = 16; off > 0; off >>= 1) s += __shfl_down_sync(0xffffffffu, s, off);
        if (lane == 0) out[warp * OUT_ + o] = s + bias[o];
    }
}

// ---------------------------------------------------------------------------
extern "C" void kernel_launch(void* const* d_in, const int* in_sizes, int n_in,
                              void* d_out, int out_size)
{
    const float* x   = (const float*)d_in[0];
    const float* W0  = (const float*)d_in[1];
    const float* v0  = (const float*)d_in[2];
    const float* b0  = (const float*)d_in[3];
    const float* W1  = (const float*)d_in[4];
    const float* v1  = (const float*)d_in[5];
    const float* b1  = (const float*)d_in[6];
    const float* fcw = (const float*)d_in[7];
    const float* fcb = (const float*)d_in[8];
    float* out = (float*)d_out;

    float *pU, *pH2;
    __nv_bfloat16 *pAhi, *pAlo, *pBhi, *pBlo;
    cudaGetSymbolAddress((void**)&pU,   g_U);
    cudaGetSymbolAddress((void**)&pAhi, g_Ahi);
    cudaGetSymbolAddress((void**)&pAlo, g_Alo);
    cudaGetSymbolAddress((void**)&pBhi, g_BtHi);
    cudaGetSymbolAddress((void**)&pBlo, g_BtLo);
    cudaGetSymbolAddress((void**)&pH2,  g_h2);

    cudaFuncSetAttribute(gemm_hmma<128>, cudaFuncAttributeMaxDynamicSharedMemorySize, GEMM_SMEM);
    cudaFuncSetAttribute(gemm_hmma<512>, cudaFuncAttributeMaxDynamicSharedMemorySize, GEMM_SMEM);

    const dim3 gemmGrid(N3_ / 256, M_ / 128);   // (6, 512) — n fast for A L2 reuse

    // ---- Layer 0 ----
    split_kernel<<<(M_ * D_ / 4 + 255) / 256, 256>>>(x, pAhi, pAlo, M_ * D_ / 4);
    splitT_kernel<<<(D_ * N3_ + 255) / 256, 256>>>(W0, pBhi, pBlo, D_);
    gemm_hmma<128><<<gemmGrid, 256, GEMM_SMEM>>>(pAhi, pAlo, pBhi, pBlo, pU);
    rec0_kernel<<<(B_ * H_) / 256, 256>>>(pU, v0, b0, pAhi, pAlo);  // h1 directly as bf16 hi/lo

    // ---- Layer 1 ----
    splitT_kernel<<<(H_ * N3_ + 255) / 256, 256>>>(W1, pBhi, pBlo, H_);
    gemm_hmma<512><<<gemmGrid, 256, GEMM_SMEM>>>(pAhi, pAlo, pBhi, pBlo, pU);
    rec1_kernel<<<(B_ * H_) / 256, 256>>>(pU, v1, b1, pH2);

    // ---- Head ----
    fc_kernel<<<(B_ * 32 + 255) / 256, 256>>>(pH2, fcw, fcb, out);
}

// round 9
// speedup vs baseline: 1.1662x; 1.1662x over previous
#include <cuda_runtime.h>
#include <cuda_bf16.h>
#include <cstdint>

#define L_   512
#define B_   128
#define D_   128
#define H_   512
#define OUT_ 5
#define M_   (L_*B_)     // 65536 rows
#define N3_  (3*H_)      // 1536 cols

// ---------------------------------------------------------------------------
// Static device scratch (no cudaMalloc allowed)
// ---------------------------------------------------------------------------
__device__ float         g_U   [(size_t)M_ * N3_];          // 402 MB
__device__ __nv_bfloat16 g_Ahi [(size_t)M_ * H_];           // 64 MB (x split / h1 hi)
__device__ __nv_bfloat16 g_Alo [(size_t)M_ * H_];           // 64 MB (x split / h1 lo)
__device__ __nv_bfloat16 g_BtHi[(size_t)N3_ * H_];          // 1.5 MB
__device__ __nv_bfloat16 g_BtLo[(size_t)N3_ * H_];
__device__ float         g_h2  [B_ * H_];

// ---------------------------------------------------------------------------
// Helpers (base-ISA only: ldmatrix / mma.sync / cp.async — no 'a' features)
// ---------------------------------------------------------------------------
__device__ __forceinline__ uint32_t smem_to_u32(const void* p) {
    uint32_t a;
    asm("{ .reg .u64 t; cvta.to.shared.u64 t, %1; cvt.u32.u64 %0, t; }" : "=r"(a) : "l"(p));
    return a;
}
#define SW128(bo) ((bo) ^ (((bo) >> 3) & 0x70))

__device__ __forceinline__ void cp_async16(uint32_t dst, const void* src) {
    asm volatile("cp.async.cg.shared.global [%0], [%1], 16;" :: "r"(dst), "l"(src) : "memory");
}
__device__ __forceinline__ void cp_commit() {
    asm volatile("cp.async.commit_group;" ::: "memory");
}
template<int N>
__device__ __forceinline__ void cp_wait() {
    asm volatile("cp.async.wait_group %0;" :: "n"(N) : "memory");
}
__device__ __forceinline__ void ldm_x4(uint32_t& r0, uint32_t& r1, uint32_t& r2, uint32_t& r3,
                                       uint32_t addr) {
    asm volatile("ldmatrix.sync.aligned.m8n8.x4.shared.b16 {%0,%1,%2,%3}, [%4];"
                 : "=r"(r0), "=r"(r1), "=r"(r2), "=r"(r3) : "r"(addr));
}
__device__ __forceinline__ void mma_bf16(float* c, const uint32_t* a, const uint32_t* b) {
    asm volatile(
        "mma.sync.aligned.m16n8k16.row.col.f32.bf16.bf16.f32 "
        "{%0,%1,%2,%3}, {%4,%5,%6,%7}, {%8,%9}, {%0,%1,%2,%3};"
        : "+f"(c[0]), "+f"(c[1]), "+f"(c[2]), "+f"(c[3])
        : "r"(a[0]), "r"(a[1]), "r"(a[2]), "r"(a[3]), "r"(b[0]), "r"(b[1]));
}
__device__ __forceinline__ void stcs2(float* p, float x, float y) {
    asm volatile("st.global.cs.v2.f32 [%0], {%1, %2};" :: "l"(p), "f"(x), "f"(y) : "memory");
}

// ---------------------------------------------------------------------------
// GEMM: C[M x N3] = (Ahi+Alo)[M x K] @ (Bhi+Blo)^T[N3 x K], fp32-via-3xbf16.
// CTA tile 128x256, BK=64, 8 warps (2m x 4n), warp tile 64x64.
// SMEM/stage: Ahi|Alo (16KB each) + Bhi|Blo (32KB each) = 96KB, 2 stages.
// Products staged hi*hi -> hi*lo -> lo*hi to bound register pressure.
// ---------------------------------------------------------------------------
#define OFF_AHI  0
#define OFF_ALO  16384
#define OFF_BHI  32768
#define OFF_BLO  65536
#define STAGE_B  98304                 // 96 KB
#define GEMM_SMEM (2*STAGE_B)          // 192 KB

template<int KTOT>
__device__ __forceinline__ void load_stage(uint32_t sb, int buf, int kt,
    const __nv_bfloat16* __restrict__ Ahi, const __nv_bfloat16* __restrict__ Alo,
    const __nv_bfloat16* __restrict__ Bhi, const __nv_bfloat16* __restrict__ Blo,
    int rowBase, int colBase, int tid)
{
    const uint32_t base = sb + buf * STAGE_B;
    const int kOff = kt * 64;
    #pragma unroll
    for (int i = 0; i < 4; i++) {                 // A: 128 rows x 128B, hi+lo
        const int ci = tid + i * 256;
        const int row = ci >> 3, c8 = ci & 7;
        const size_t g = (size_t)(rowBase + row) * KTOT + kOff + c8 * 8;
        const uint32_t so = SW128((uint32_t)(row * 128 + c8 * 16));
        cp_async16(base + OFF_AHI + so, Ahi + g);
        cp_async16(base + OFF_ALO + so, Alo + g);
    }
    #pragma unroll
    for (int i = 0; i < 8; i++) {                 // B: 256 rows x 128B, hi+lo
        const int ci = tid + i * 256;
        const int row = ci >> 3, c8 = ci & 7;
        const size_t g = (size_t)(colBase + row) * KTOT + kOff + c8 * 8;
        const uint32_t so = SW128((uint32_t)(row * 128 + c8 * 16));
        cp_async16(base + OFF_BHI + so, Bhi + g);
        cp_async16(base + OFF_BLO + so, Blo + g);
    }
}

__device__ __forceinline__ void compute_stage(uint32_t sb, int buf,
    int warp_m, int warp_n, int lane, float acc[4][8][4])
{
    const uint32_t base = sb + buf * STAGE_B;
    const int mrow = warp_m * 64 + (lane & 15);
    const int bg = lane >> 3, brr = lane & 7;
    #pragma unroll
    for (int k16 = 0; k16 < 4; k16++) {
        const int kc = k16 * 2 + (lane >> 4);
        uint32_t af[4][4];   // A fragments (reused for hi then lo)
        uint32_t bhi[8][2];  // B hi fragments (live across all 3 products)
        uint32_t bx[8][2];   // B lo fragments (short-lived)

        // --- A hi * B hi ---
        #pragma unroll
        for (int ma = 0; ma < 4; ma++) {
            const uint32_t so = SW128((uint32_t)((mrow + ma * 16) * 128 + kc * 16));
            ldm_x4(af[ma][0], af[ma][1], af[ma][2], af[ma][3], base + OFF_AHI + so);
        }
        #pragma unroll
        for (int ng = 0; ng < 4; ng++) {
            const int n = warp_n * 64 + ng * 16 + (bg >> 1) * 8 + brr;
            const uint32_t so = SW128((uint32_t)(n * 128 + (k16 * 2 + (bg & 1)) * 16));
            uint32_t r0, r1, r2, r3;
            ldm_x4(r0, r1, r2, r3, base + OFF_BHI + so);
            bhi[ng*2][0] = r0; bhi[ng*2][1] = r1; bhi[ng*2+1][0] = r2; bhi[ng*2+1][1] = r3;
        }
        #pragma unroll
        for (int ma = 0; ma < 4; ma++)
            #pragma unroll
            for (int na = 0; na < 8; na++) mma_bf16(acc[ma][na], af[ma], bhi[na]);

        // --- A hi * B lo ---
        #pragma unroll
        for (int ng = 0; ng < 4; ng++) {
            const int n = warp_n * 64 + ng * 16 + (bg >> 1) * 8 + brr;
            const uint32_t so = SW128((uint32_t)(n * 128 + (k16 * 2 + (bg & 1)) * 16));
            uint32_t r0, r1, r2, r3;
            ldm_x4(r0, r1, r2, r3, base + OFF_BLO + so);
            bx[ng*2][0] = r0; bx[ng*2][1] = r1; bx[ng*2+1][0] = r2; bx[ng*2+1][1] = r3;
        }
        #pragma unroll
        for (int ma = 0; ma < 4; ma++)
            #pragma unroll
            for (int na = 0; na < 8; na++) mma_bf16(acc[ma][na], af[ma], bx[na]);

        // --- A lo * B hi ---
        #pragma unroll
        for (int ma = 0; ma < 4; ma++) {
            const uint32_t so = SW128((uint32_t)((mrow + ma * 16) * 128 + kc * 16));
            ldm_x4(af[ma][0], af[ma][1], af[ma][2], af[ma][3], base + OFF_ALO + so);
        }
        #pragma unroll
        for (int ma = 0; ma < 4; ma++)
            #pragma unroll
            for (int na = 0; na < 8; na++) mma_bf16(acc[ma][na], af[ma], bhi[na]);
    }
}

template<int KTOT>
__global__ __launch_bounds__(256, 1)
void gemm_hmma(const __nv_bfloat16* __restrict__ Ahi,
               const __nv_bfloat16* __restrict__ Alo,
               const __nv_bfloat16* __restrict__ Bhi,
               const __nv_bfloat16* __restrict__ Blo,
               float* __restrict__ C)
{
    extern __shared__ char smem[];
    const uint32_t sb = smem_to_u32(smem);
    const int tid = threadIdx.x, wid = tid >> 5, lane = tid & 31;
    const int warp_m = wid & 1, warp_n = wid >> 1;
    const int rowBase = blockIdx.y << 7;
    const int colBase = blockIdx.x << 8;
    constexpr int KT = KTOT / 64;

    float acc[4][8][4];
    #pragma unroll
    for (int i = 0; i < 4; i++)
        #pragma unroll
        for (int j = 0; j < 8; j++)
            #pragma unroll
            for (int k = 0; k < 4; k++) acc[i][j][k] = 0.f;

    load_stage<KTOT>(sb, 0, 0, Ahi, Alo, Bhi, Blo, rowBase, colBase, tid);
    cp_commit();

    #pragma unroll 1
    for (int kt = 0; kt < KT; kt++) {
        if (kt + 1 < KT) {
            load_stage<KTOT>(sb, (kt + 1) & 1, kt + 1, Ahi, Alo, Bhi, Blo,
                             rowBase, colBase, tid);
            cp_commit();
            cp_wait<1>();
        } else {
            cp_wait<0>();
        }
        __syncthreads();
        compute_stage(sb, kt & 1, warp_m, warp_n, lane, acc);
        __syncthreads();
    }

    // Epilogue: streaming fp32 stores (C is written once, read once by rec)
    const int mBase = rowBase + warp_m * 64 + (lane >> 2);
    const int nBase = colBase + warp_n * 64 + (lane & 3) * 2;
    #pragma unroll
    for (int ma = 0; ma < 4; ma++) {
        #pragma unroll
        for (int na = 0; na < 8; na++) {
            const int m = mBase + ma * 16;
            const int n = nBase + na * 8;
            stcs2(C + (size_t)m * N3_ + n,       acc[ma][na][0], acc[ma][na][1]);
            stcs2(C + (size_t)(m + 8) * N3_ + n, acc[ma][na][2], acc[ma][na][3]);
        }
    }
}

// ---------------------------------------------------------------------------
// Split fp32 -> bf16 hi/lo (elementwise, float4-vectorized)
// ---------------------------------------------------------------------------
__global__ void split_kernel(const float* __restrict__ src,
                             __nv_bfloat16* __restrict__ hi,
                             __nv_bfloat16* __restrict__ lo, int n4)
{
    const int i = blockIdx.x * blockDim.x + threadIdx.x;
    if (i >= n4) return;
    const float4 v = reinterpret_cast<const float4*>(src)[i];
    float f[4] = {v.x, v.y, v.z, v.w};
    __nv_bfloat16 h[4], l[4];
    #pragma unroll
    for (int j = 0; j < 4; j++) {
        h[j] = __float2bfloat16(f[j]);
        l[j] = __float2bfloat16(f[j] - __bfloat162float(h[j]));
    }
    __nv_bfloat162* hp = reinterpret_cast<__nv_bfloat162*>(hi + 4 * (size_t)i);
    __nv_bfloat162* lp = reinterpret_cast<__nv_bfloat162*>(lo + 4 * (size_t)i);
    hp[0] = __nv_bfloat162(h[0], h[1]); hp[1] = __nv_bfloat162(h[2], h[3]);
    lp[0] = __nv_bfloat162(l[0], l[1]); lp[1] = __nv_bfloat162(l[2], l[3]);
}

// Transpose + split: W[K, N3] fp32 -> hiT/loT[N3, K] bf16
__global__ void splitT_kernel(const float* __restrict__ W,
                              __nv_bfloat16* __restrict__ hiT,
                              __nv_bfloat16* __restrict__ loT, int K)
{
    const int idx = blockIdx.x * blockDim.x + threadIdx.x;
    if (idx >= K * N3_) return;
    const int k = idx / N3_, n = idx % N3_;
    const float f = W[idx];
    const __nv_bfloat16 h = __float2bfloat16(f);
    hiT[(size_t)n * K + k] = h;
    loT[(size_t)n * K + k] = __float2bfloat16(f - __bfloat162float(h));
}

// ---------------------------------------------------------------------------
// SRU recurrence, software-pipelined (prefetch next 4-t batch before compute)
// R6-proven form: all register arrays statically indexed (no local-mem demotion)
// ---------------------------------------------------------------------------
__device__ __forceinline__ float sigmoidf_(float z) { return 1.f / (1.f + __expf(-z)); }

__global__ __launch_bounds__(256)
void rec0_kernel(const float* __restrict__ U, const float* __restrict__ v,
                 const float* __restrict__ bias,
                 __nv_bfloat16* __restrict__ hHi, __nv_bfloat16* __restrict__ hLo)
{
    const int tid = blockIdx.x * blockDim.x + threadIdx.x;
    const int b = tid >> 9, h = tid & (H_ - 1);
    const float vf = v[h], vr = v[H_ + h];
    const float bf = bias[h], br = bias[H_ + h];
    float c = 0.f;
    float a0[4], a1[4], a2[4];
    #pragma unroll
    for (int i = 0; i < 4; i++) {
        const size_t base = ((size_t)i * B_ + b) * N3_ + h;
        a0[i] = __ldcs(U + base); a1[i] = __ldcs(U + base + H_); a2[i] = __ldcs(U + base + 2*H_);
    }
    for (int t0 = 0; t0 < L_; t0 += 4) {
        float n0[4] = {0,0,0,0}, n1[4] = {0,0,0,0}, n2[4] = {0,0,0,0};
        if (t0 + 4 < L_) {
            #pragma unroll
            for (int i = 0; i < 4; i++) {
                const size_t base = ((size_t)(t0 + 4 + i) * B_ + b) * N3_ + h;
                n0[i] = __ldcs(U + base); n1[i] = __ldcs(U + base + H_); n2[i] = __ldcs(U + base + 2*H_);
            }
        }
        #pragma unroll
        for (int i = 0; i < 4; i++) {
            const float f = sigmoidf_(a1[i] + vf * c + bf);
            const float r = sigmoidf_(a2[i] + vr * c + br);
            c = f * c + (1.f - f) * a0[i];
            const float hv = r * c;
            const __nv_bfloat16 hb = __float2bfloat16(hv);
            const size_t o = ((size_t)(t0 + i) * B_ + b) * H_ + h;
            __stcs(hHi + o, hb);
            __stcs(hLo + o, __float2bfloat16(hv - __bfloat162float(hb)));
        }
        #pragma unroll
        for (int i = 0; i < 4; i++) { a0[i] = n0[i]; a1[i] = n1[i]; a2[i] = n2[i]; }
    }
}

__global__ __launch_bounds__(256)
void rec1_kernel(const float* __restrict__ U, const float* __restrict__ v,
                 const float* __restrict__ bias, float* __restrict__ hout)
{
    const int tid = blockIdx.x * blockDim.x + threadIdx.x;
    const int b = tid >> 9, h = tid & (H_ - 1);
    const float vf = v[h], vr = v[H_ + h];
    const float bf = bias[h], br = bias[H_ + h];
    float c = 0.f, hlast = 0.f;
    float a0[4], a1[4], a2[4];
    #pragma unroll
    for (int i = 0; i < 4; i++) {
        const size_t base = ((size_t)i * B_ + b) * N3_ + h;
        a0[i] = __ldcs(U + base); a1[i] = __ldcs(U + base + H_); a2[i] = __ldcs(U + base + 2*H_);
    }
    for (int t0 = 0; t0 < L_; t0 += 4) {
        float n0[4] = {0,0,0,0}, n1[4] = {0,0,0,0}, n2[4] = {0,0,0,0};
        if (t0 + 4 < L_) {
            #pragma unroll
            for (int i = 0; i < 4; i++) {
                const size_t base = ((size_t)(t0 + 4 + i) * B_ + b) * N3_ + h;
                n0[i] = __ldcs(U + base); n1[i] = __ldcs(U + base + H_); n2[i] = __ldcs(U + base + 2*H_);
            }
        }
        #pragma unroll
        for (int i = 0; i < 4; i++) {
            const float f = sigmoidf_(a1[i] + vf * c + bf);
            const float r = sigmoidf_(a2[i] + vr * c + br);
            c = f * c + (1.f - f) * a0[i];
            hlast = r * c;
        }
        #pragma unroll
        for (int i = 0; i < 4; i++) { a0[i] = n0[i]; a1[i] = n1[i]; a2[i] = n2[i]; }
    }
    hout[b * H_ + h] = hlast;
}

// ---------------------------------------------------------------------------
// Final FC: out[b,o] = h2[b,:] . fc_w[o,:] + fc_b[o]
// ---------------------------------------------------------------------------
__global__ void fc_kernel(const float* __restrict__ h2, const float* __restrict__ w,
                          const float* __restrict__ bias, float* __restrict__ out)
{
    const int gtid = blockIdx.x * blockDim.x + threadIdx.x;
    const int warp = gtid >> 5, lane = gtid & 31;
    if (warp >= B_) return;
    #pragma unroll
    for (int o = 0; o < OUT_; o++) {
        float s = 0.f;
        for (int h = lane; h < H_; h += 32) s += h2[warp * H_ + h] * w[o * H_ + h];
        #pragma unroll
        for (int off = 16; off > 0; off >>= 1) s += __shfl_down_sync(0xffffffffu, s, off);
        if (lane == 0) out[warp * OUT_ + o] = s + bias[o];
    }
}

// ---------------------------------------------------------------------------
extern "C" void kernel_launch(void* const* d_in, const int* in_sizes, int n_in,
                              void* d_out, int out_size)
{
    const float* x   = (const float*)d_in[0];
    const float* W0  = (const float*)d_in[1];
    const float* v0  = (const float*)d_in[2];
    const float* b0  = (const float*)d_in[3];
    const float* W1  = (const float*)d_in[4];
    const float* v1  = (const float*)d_in[5];
    const float* b1  = (const float*)d_in[6];
    const float* fcw = (const float*)d_in[7];
    const float* fcb = (const float*)d_in[8];
    float* out = (float*)d_out;

    float *pU, *pH2;
    __nv_bfloat16 *pAhi, *pAlo, *pBhi, *pBlo;
    cudaGetSymbolAddress((void**)&pU,   g_U);
    cudaGetSymbolAddress((void**)&pAhi, g_Ahi);
    cudaGetSymbolAddress((void**)&pAlo, g_Alo);
    cudaGetSymbolAddress((void**)&pBhi, g_BtHi);
    cudaGetSymbolAddress((void**)&pBlo, g_BtLo);
    cudaGetSymbolAddress((void**)&pH2,  g_h2);

    cudaFuncSetAttribute(gemm_hmma<128>, cudaFuncAttributeMaxDynamicSharedMemorySize, GEMM_SMEM);
    cudaFuncSetAttribute(gemm_hmma<512>, cudaFuncAttributeMaxDynamicSharedMemorySize, GEMM_SMEM);

    const dim3 gemmGrid(N3_ / 256, M_ / 128);   // (6, 512) — n fast for A L2 reuse

    // ---- Layer 0 ----
    split_kernel<<<(M_ * D_ / 4 + 255) / 256, 256>>>(x, pAhi, pAlo, M_ * D_ / 4);
    splitT_kernel<<<(D_ * N3_ + 255) / 256, 256>>>(W0, pBhi, pBlo, D_);
    gemm_hmma<128><<<gemmGrid, 256, GEMM_SMEM>>>(pAhi, pAlo, pBhi, pBlo, pU);
    rec0_kernel<<<(B_ * H_) / 256, 256>>>(pU, v0, b0, pAhi, pAlo);  // h1 directly as bf16 hi/lo

    // ---- Layer 1 ----
    splitT_kernel<<<(H_ * N3_ + 255) / 256, 256>>>(W1, pBhi, pBlo, H_);
    gemm_hmma<512><<<gemmGrid, 256, GEMM_SMEM>>>(pAhi, pAlo, pBhi, pBlo, pU);
    rec1_kernel<<<(B_ * H_) / 256, 256>>>(pU, v1, b1, pH2);

    // ---- Head ----
    fc_kernel<<<(B_ * 32 + 255) / 256, 256>>>(pH2, fcw, fcb, out);
}

// round 13
// speedup vs baseline: 1.2040x; 1.0324x over previous
#include <cuda_runtime.h>
#include <cuda_bf16.h>
#include <cstdint>

#define L_   512
#define B_   128
#define D_   128
#define H_   512
#define OUT_ 5
#define M_   (L_*B_)     // 65536 rows
#define N3_  (3*H_)      // 1536 cols

// ---------------------------------------------------------------------------
// Static device scratch (no cudaMalloc allowed)
// ---------------------------------------------------------------------------
__device__ float         g_U   [(size_t)M_ * N3_];          // 402 MB
__device__ __nv_bfloat16 g_Ahi [(size_t)M_ * H_];           // 64 MB (x split / h1 hi)
__device__ __nv_bfloat16 g_Alo [(size_t)M_ * H_];           // 64 MB (x split / h1 lo)
__device__ __nv_bfloat16 g_BtHi[(size_t)N3_ * H_];          // 1.5 MB
__device__ __nv_bfloat16 g_BtLo[(size_t)N3_ * H_];
__device__ float         g_h2  [B_ * H_];

// ---------------------------------------------------------------------------
// Helpers (base-ISA only: ldmatrix / mma.sync / cp.async — no 'a' features)
// ---------------------------------------------------------------------------
__device__ __forceinline__ uint32_t smem_to_u32(const void* p) {
    uint32_t a;
    asm("{ .reg .u64 t; cvta.to.shared.u64 t, %1; cvt.u32.u64 %0, t; }" : "=r"(a) : "l"(p));
    return a;
}
// 64B-row swizzle (Swizzle<2,4,2>): rows 0..7 land on 8 distinct 16B columns
#define SW64(bo) ((bo) ^ (((bo) >> 3) & 0x30))

__device__ __forceinline__ void cp_async16(uint32_t dst, const void* src) {
    asm volatile("cp.async.cg.shared.global [%0], [%1], 16;" :: "r"(dst), "l"(src) : "memory");
}
__device__ __forceinline__ void cp_commit() {
    asm volatile("cp.async.commit_group;" ::: "memory");
}
template<int N>
__device__ __forceinline__ void cp_wait() {
    asm volatile("cp.async.wait_group %0;" :: "n"(N) : "memory");
}
__device__ __forceinline__ void ldm_x4(uint32_t& r0, uint32_t& r1, uint32_t& r2, uint32_t& r3,
                                       uint32_t addr) {
    asm volatile("ldmatrix.sync.aligned.m8n8.x4.shared.b16 {%0,%1,%2,%3}, [%4];"
                 : "=r"(r0), "=r"(r1), "=r"(r2), "=r"(r3) : "r"(addr));
}
__device__ __forceinline__ void mma_bf16(float* c, const uint32_t* a, const uint32_t* b) {
    asm volatile(
        "mma.sync.aligned.m16n8k16.row.col.f32.bf16.bf16.f32 "
        "{%0,%1,%2,%3}, {%4,%5,%6,%7}, {%8,%9}, {%0,%1,%2,%3};"
        : "+f"(c[0]), "+f"(c[1]), "+f"(c[2]), "+f"(c[3])
        : "r"(a[0]), "r"(a[1]), "r"(a[2]), "r"(a[3]), "r"(b[0]), "r"(b[1]));
}
__device__ __forceinline__ void stcs2(float* p, float x, float y) {
    asm volatile("st.global.cs.v2.f32 [%0], {%1, %2};" :: "l"(p), "f"(x), "f"(y) : "memory");
}

// ---------------------------------------------------------------------------
// GEMM: C[M x N3] = (Ahi+Alo)[M x K] @ (Bhi+Blo)^T[N3 x K], fp32-via-3xbf16.
// CTA tile 128x128, BK=32, 8 warps (2m x 4n), warp tile 64x32.
// 3-stage cp.async pipeline, 32KB/stage (96KB total) -> 2 CTAs/SM.
// Products staged hi*hi -> hi*lo -> lo*hi; acc = 64 regs/thread.
// ---------------------------------------------------------------------------
#define OFF_AHI  0
#define OFF_ALO  8192
#define OFF_BHI  16384
#define OFF_BLO  24576
#define STAGE_B  32768                 // 32 KB
#define GEMM_SMEM (3*STAGE_B)          // 96 KB

template<int KTOT>
__device__ __forceinline__ void load_stage(uint32_t sb, int buf, int kt,
    const __nv_bfloat16* __restrict__ Ahi, const __nv_bfloat16* __restrict__ Alo,
    const __nv_bfloat16* __restrict__ Bhi, const __nv_bfloat16* __restrict__ Blo,
    int rowBase, int colBase, int tid)
{
    const uint32_t base = sb + buf * STAGE_B;
    const int kOff = kt * 32;
    #pragma unroll
    for (int i = 0; i < 2; i++) {                 // A: 128 rows x 64B, hi+lo
        const int ci = tid + i * 256;             // 512 chunks of 16B per half
        const int row = ci >> 2, c4 = ci & 3;
        const size_t g = (size_t)(rowBase + row) * KTOT + kOff + c4 * 8;
        const uint32_t so = SW64((uint32_t)(row * 64 + c4 * 16));
        cp_async16(base + OFF_AHI + so, Ahi + g);
        cp_async16(base + OFF_ALO + so, Alo + g);
    }
    #pragma unroll
    for (int i = 0; i < 2; i++) {                 // B: 128 rows x 64B, hi+lo
        const int ci = tid + i * 256;
        const int row = ci >> 2, c4 = ci & 3;
        const size_t g = (size_t)(colBase + row) * KTOT + kOff + c4 * 8;
        const uint32_t so = SW64((uint32_t)(row * 64 + c4 * 16));
        cp_async16(base + OFF_BHI + so, Bhi + g);
        cp_async16(base + OFF_BLO + so, Blo + g);
    }
}

__device__ __forceinline__ void compute_stage(uint32_t sb, int buf,
    int warp_m, int warp_n, int lane, float acc[4][4][4])
{
    const uint32_t base = sb + buf * STAGE_B;
    const int mrow = warp_m * 64 + (lane & 15);
    const int bg = lane >> 3, brr = lane & 7;
    #pragma unroll
    for (int k16 = 0; k16 < 2; k16++) {
        const int kc = k16 * 2 + (lane >> 4);     // 16B column index (0..3)
        uint32_t af[4][4];   // A fragments (hi, then reloaded as lo)
        uint32_t bhi[4][2];  // B hi fragments (live across all 3 products)
        uint32_t bx[4][2];   // B lo fragments

        // --- A hi * B hi ---
        #pragma unroll
        for (int ma = 0; ma < 4; ma++) {
            const uint32_t so = SW64((uint32_t)((mrow + ma * 16) * 64 + kc * 16));
            ldm_x4(af[ma][0], af[ma][1], af[ma][2], af[ma][3], base + OFF_AHI + so);
        }
        #pragma unroll
        for (int ng = 0; ng < 2; ng++) {
            const int n = warp_n * 32 + ng * 16 + (bg >> 1) * 8 + brr;
            const uint32_t so = SW64((uint32_t)(n * 64 + (k16 * 2 + (bg & 1)) * 16));
            uint32_t r0, r1, r2, r3;
            ldm_x4(r0, r1, r2, r3, base + OFF_BHI + so);
            bhi[ng*2][0] = r0; bhi[ng*2][1] = r1; bhi[ng*2+1][0] = r2; bhi[ng*2+1][1] = r3;
        }
        #pragma unroll
        for (int ma = 0; ma < 4; ma++)
            #pragma unroll
            for (int na = 0; na < 4; na++) mma_bf16(acc[ma][na], af[ma], bhi[na]);

        // --- A hi * B lo ---
        #pragma unroll
        for (int ng = 0; ng < 2; ng++) {
            const int n = warp_n * 32 + ng * 16 + (bg >> 1) * 8 + brr;
            const uint32_t so = SW64((uint32_t)(n * 64 + (k16 * 2 + (bg & 1)) * 16));
            uint32_t r0, r1, r2, r3;
            ldm_x4(r0, r1, r2, r3, base + OFF_BLO + so);
            bx[ng*2][0] = r0; bx[ng*2][1] = r1; bx[ng*2+1][0] = r2; bx[ng*2+1][1] = r3;
        }
        #pragma unroll
        for (int ma = 0; ma < 4; ma++)
            #pragma unroll
            for (int na = 0; na < 4; na++) mma_bf16(acc[ma][na], af[ma], bx[na]);

        // --- A lo * B hi ---
        #pragma unroll
        for (int ma = 0; ma < 4; ma++) {
            const uint32_t so = SW64((uint32_t)((mrow + ma * 16) * 64 + kc * 16));
            ldm_x4(af[ma][0], af[ma][1], af[ma][2], af[ma][3], base + OFF_ALO + so);
        }
        #pragma unroll
        for (int ma = 0; ma < 4; ma++)
            #pragma unroll
            for (int na = 0; na < 4; na++) mma_bf16(acc[ma][na], af[ma], bhi[na]);
    }
}

template<int KTOT>
__global__ __launch_bounds__(256, 2)
void gemm_hmma(const __nv_bfloat16* __restrict__ Ahi,
               const __nv_bfloat16* __restrict__ Alo,
               const __nv_bfloat16* __restrict__ Bhi,
               const __nv_bfloat16* __restrict__ Blo,
               float* __restrict__ C)
{
    extern __shared__ char smem[];
    const uint32_t sb = smem_to_u32(smem);
    const int tid = threadIdx.x, wid = tid >> 5, lane = tid & 31;
    const int warp_m = wid & 1, warp_n = wid >> 1;
    const int rowBase = blockIdx.y << 7;
    const int colBase = blockIdx.x << 7;
    constexpr int KT = KTOT / 32;

    float acc[4][4][4];
    #pragma unroll
    for (int i = 0; i < 4; i++)
        #pragma unroll
        for (int j = 0; j < 4; j++)
            #pragma unroll
            for (int k = 0; k < 4; k++) acc[i][j][k] = 0.f;

    load_stage<KTOT>(sb, 0, 0, Ahi, Alo, Bhi, Blo, rowBase, colBase, tid);
    cp_commit();
    load_stage<KTOT>(sb, 1, 1, Ahi, Alo, Bhi, Blo, rowBase, colBase, tid);
    cp_commit();

    int buf = 0;
    #pragma unroll 1
    for (int kt = 0; kt < KT; kt++) {
        if (kt + 1 < KT) cp_wait<1>(); else cp_wait<0>();
        __syncthreads();                          // stage kt ready; compute kt-1 done
        if (kt + 2 < KT) {
            int nb = buf + 2; if (nb >= 3) nb -= 3;
            load_stage<KTOT>(sb, nb, kt + 2, Ahi, Alo, Bhi, Blo, rowBase, colBase, tid);
            cp_commit();
        }
        compute_stage(sb, buf, warp_m, warp_n, lane, acc);
        if (++buf == 3) buf = 0;
    }

    // Epilogue: streaming fp32 stores (C is written once, read once by rec)
    const int mBase = rowBase + warp_m * 64 + (lane >> 2);
    const int nBase = colBase + warp_n * 32 + (lane & 3) * 2;
    #pragma unroll
    for (int ma = 0; ma < 4; ma++) {
        #pragma unroll
        for (int na = 0; na < 4; na++) {
            const int m = mBase + ma * 16;
            const int n = nBase + na * 8;
            stcs2(C + (size_t)m * N3_ + n,       acc[ma][na][0], acc[ma][na][1]);
            stcs2(C + (size_t)(m + 8) * N3_ + n, acc[ma][na][2], acc[ma][na][3]);
        }
    }
}

// ---------------------------------------------------------------------------
// Split fp32 -> bf16 hi/lo (elementwise, float4-vectorized)
// ---------------------------------------------------------------------------
__global__ void split_kernel(const float* __restrict__ src,
                             __nv_bfloat16* __restrict__ hi,
                             __nv_bfloat16* __restrict__ lo, int n4)
{
    const int i = blockIdx.x * blockDim.x + threadIdx.x;
    if (i >= n4) return;
    const float4 v = reinterpret_cast<const float4*>(src)[i];
    float f[4] = {v.x, v.y, v.z, v.w};
    __nv_bfloat16 h[4], l[4];
    #pragma unroll
    for (int j = 0; j < 4; j++) {
        h[j] = __float2bfloat16(f[j]);
        l[j] = __float2bfloat16(f[j] - __bfloat162float(h[j]));
    }
    __nv_bfloat162* hp = reinterpret_cast<__nv_bfloat162*>(hi + 4 * (size_t)i);
    __nv_bfloat162* lp = reinterpret_cast<__nv_bfloat162*>(lo + 4 * (size_t)i);
    hp[0] = __nv_bfloat162(h[0], h[1]); hp[1] = __nv_bfloat162(h[2], h[3]);
    lp[0] = __nv_bfloat162(l[0], l[1]); lp[1] = __nv_bfloat162(l[2], l[3]);
}

// Transpose + split: W[K, N3] fp32 -> hiT/loT[N3, K] bf16
__global__ void splitT_kernel(const float* __restrict__ W,
                              __nv_bfloat16* __restrict__ hiT,
                              __nv_bfloat16* __restrict__ loT, int K)
{
    const int idx = blockIdx.x * blockDim.x + threadIdx.x;
    if (idx >= K * N3_) return;
    const int k = idx / N3_, n = idx % N3_;
    const float f = W[idx];
    const __nv_bfloat16 h = __float2bfloat16(f);
    hiT[(size_t)n * K + k] = h;
    loT[(size_t)n * K + k] = __float2bfloat16(f - __bfloat162float(h));
}

// ---------------------------------------------------------------------------
// SRU recurrence, software-pipelined (prefetch next 4-t batch before compute)
// R6-proven form: all register arrays statically indexed (no local-mem demotion)
// ---------------------------------------------------------------------------
__device__ __forceinline__ float sigmoidf_(float z) { return 1.f / (1.f + __expf(-z)); }

__global__ __launch_bounds__(256)
void rec0_kernel(const float* __restrict__ U, const float* __restrict__ v,
                 const float* __restrict__ bias,
                 __nv_bfloat16* __restrict__ hHi, __nv_bfloat16* __restrict__ hLo)
{
    const int tid = blockIdx.x * blockDim.x + threadIdx.x;
    const int b = tid >> 9, h = tid & (H_ - 1);
    const float vf = v[h], vr = v[H_ + h];
    const float bf = bias[h], br = bias[H_ + h];
    float c = 0.f;
    float a0[4], a1[4], a2[4];
    #pragma unroll
    for (int i = 0; i < 4; i++) {
        const size_t base = ((size_t)i * B_ + b) * N3_ + h;
        a0[i] = __ldcs(U + base); a1[i] = __ldcs(U + base + H_); a2[i] = __ldcs(U + base + 2*H_);
    }
    for (int t0 = 0; t0 < L_; t0 += 4) {
        float n0[4] = {0,0,0,0}, n1[4] = {0,0,0,0}, n2[4] = {0,0,0,0};
        if (t0 + 4 < L_) {
            #pragma unroll
            for (int i = 0; i < 4; i++) {
                const size_t base = ((size_t)(t0 + 4 + i) * B_ + b) * N3_ + h;
                n0[i] = __ldcs(U + base); n1[i] = __ldcs(U + base + H_); n2[i] = __ldcs(U + base + 2*H_);
            }
        }
        #pragma unroll
        for (int i = 0; i < 4; i++) {
            const float f = sigmoidf_(a1[i] + vf * c + bf);
            const float r = sigmoidf_(a2[i] + vr * c + br);
            c = f * c + (1.f - f) * a0[i];
            const float hv = r * c;
            const __nv_bfloat16 hb = __float2bfloat16(hv);
            const size_t o = ((size_t)(t0 + i) * B_ + b) * H_ + h;
            __stcs(hHi + o, hb);
            __stcs(hLo + o, __float2bfloat16(hv - __bfloat162float(hb)));
        }
        #pragma unroll
        for (int i = 0; i < 4; i++) { a0[i] = n0[i]; a1[i] = n1[i]; a2[i] = n2[i]; }
    }
}

__global__ __launch_bounds__(256)
void rec1_kernel(const float* __restrict__ U, const float* __restrict__ v,
                 const float* __restrict__ bias, float* __restrict__ hout)
{
    const int tid = blockIdx.x * blockDim.x + threadIdx.x;
    const int b = tid >> 9, h = tid & (H_ - 1);
    const float vf = v[h], vr = v[H_ + h];
    const float bf = bias[h], br = bias[H_ + h];
    float c = 0.f, hlast = 0.f;
    float a0[4], a1[4], a2[4];
    #pragma unroll
    for (int i = 0; i < 4; i++) {
        const size_t base = ((size_t)i * B_ + b) * N3_ + h;
        a0[i] = __ldcs(U + base); a1[i] = __ldcs(U + base + H_); a2[i] = __ldcs(U + base + 2*H_);
    }
    for (int t0 = 0; t0 < L_; t0 += 4) {
        float n0[4] = {0,0,0,0}, n1[4] = {0,0,0,0}, n2[4] = {0,0,0,0};
        if (t0 + 4 < L_) {
            #pragma unroll
            for (int i = 0; i < 4; i++) {
                const size_t base = ((size_t)(t0 + 4 + i) * B_ + b) * N3_ + h;
                n0[i] = __ldcs(U + base); n1[i] = __ldcs(U + base + H_); n2[i] = __ldcs(U + base + 2*H_);
            }
        }
        #pragma unroll
        for (int i = 0; i < 4; i++) {
            const float f = sigmoidf_(a1[i] + vf * c + bf);
            const float r = sigmoidf_(a2[i] + vr * c + br);
            c = f * c + (1.f - f) * a0[i];
            hlast = r * c;
        }
        #pragma unroll
        for (int i = 0; i < 4; i++) { a0[i] = n0[i]; a1[i] = n1[i]; a2[i] = n2[i]; }
    }
    hout[b * H_ + h] = hlast;
}

// ---------------------------------------------------------------------------
// Final FC: out[b,o] = h2[b,:] . fc_w[o,:] + fc_b[o]
// ---------------------------------------------------------------------------
__global__ void fc_kernel(const float* __restrict__ h2, const float* __restrict__ w,
                          const float* __restrict__ bias, float* __restrict__ out)
{
    const int gtid = blockIdx.x * blockDim.x + threadIdx.x;
    const int warp = gtid >> 5, lane = gtid & 31;
    if (warp >= B_) return;
    #pragma unroll
    for (int o = 0; o < OUT_; o++) {
        float s = 0.f;
        for (int h = lane; h < H_; h += 32) s += h2[warp * H_ + h] * w[o * H_ + h];
        #pragma unroll
        for (int off = 16; off > 0; off >>= 1) s += __shfl_down_sync(0xffffffffu, s, off);
        if (lane == 0) out[warp * OUT_ + o] = s + bias[o];
    }
}

// ---------------------------------------------------------------------------
extern "C" void kernel_launch(void* const* d_in, const int* in_sizes, int n_in,
                              void* d_out, int out_size)
{
    const float* x   = (const float*)d_in[0];
    const float* W0  = (const float*)d_in[1];
    const float* v0  = (const float*)d_in[2];
    const float* b0  = (const float*)d_in[3];
    const float* W1  = (const float*)d_in[4];
    const float* v1  = (const float*)d_in[5];
    const float* b1  = (const float*)d_in[6];
    const float* fcw = (const float*)d_in[7];
    const float* fcb = (const float*)d_in[8];
    float* out = (float*)d_out;

    float *pU, *pH2;
    __nv_bfloat16 *pAhi, *pAlo, *pBhi, *pBlo;
    cudaGetSymbolAddress((void**)&pU,   g_U);
    cudaGetSymbolAddress((void**)&pAhi, g_Ahi);
    cudaGetSymbolAddress((void**)&pAlo, g_Alo);
    cudaGetSymbolAddress((void**)&pBhi, g_BtHi);
    cudaGetSymbolAddress((void**)&pBlo, g_BtLo);
    cudaGetSymbolAddress((void**)&pH2,  g_h2);

    cudaFuncSetAttribute(gemm_hmma<128>, cudaFuncAttributeMaxDynamicSharedMemorySize, GEMM_SMEM);
    cudaFuncSetAttribute(gemm_hmma<512>, cudaFuncAttributeMaxDynamicSharedMemorySize, GEMM_SMEM);

    const dim3 gemmGrid(N3_ / 128, M_ / 128);   // (12, 512) — n fast for A L2 reuse

    // ---- Layer 0 ----
    split_kernel<<<(M_ * D_ / 4 + 255) / 256, 256>>>(x, pAhi, pAlo, M_ * D_ / 4);
    splitT_kernel<<<(D_ * N3_ + 255) / 256, 256>>>(W0, pBhi, pBlo, D_);
    gemm_hmma<128><<<gemmGrid, 256, GEMM_SMEM>>>(pAhi, pAlo, pBhi, pBlo, pU);
    rec0_kernel<<<(B_ * H_) / 256, 256>>>(pU, v0, b0, pAhi, pAlo);  // h1 directly as bf16 hi/lo

    // ---- Layer 1 ----
    splitT_kernel<<<(H_ * N3_ + 255) / 256, 256>>>(W1, pBhi, pBlo, H_);
    gemm_hmma<512><<<gemmGrid, 256, GEMM_SMEM>>>(pAhi, pAlo, pBhi, pBlo, pU);
    rec1_kernel<<<(B_ * H_) / 256, 256>>>(pU, v1, b1, pH2);

    // ---- Head ----
    fc_kernel<<<(B_ * 32 + 255) / 256, 256>>>(pH2, fcw, fcb, out);
}

// round 14
// speedup vs baseline: 2.2779x; 1.8919x over previous
#include <cuda_runtime.h>
#include <cuda_fp16.h>
#include <cstdint>

#define L_   512
#define B_   128
#define D_   128
#define H_   512
#define OUT_ 5
#define M_   (L_*B_)     // 65536 rows
#define N3_  (3*H_)      // 1536 cols

// ---------------------------------------------------------------------------
// Static device scratch (no cudaMalloc allowed)
// ---------------------------------------------------------------------------
__device__ float  g_U  [(size_t)M_ * N3_];      // 402 MB
__device__ __half g_A16[(size_t)M_ * H_];       // 64 MB: x (M x D) then h1 (M x H)
__device__ __half g_Bt [(size_t)N3_ * H_];      // 1.5 MB: W^T fp16
__device__ float  g_h2 [B_ * H_];

// ---------------------------------------------------------------------------
// Helpers (base-ISA only: ldmatrix / mma.sync / cp.async — no 'a' features)
// ---------------------------------------------------------------------------
__device__ __forceinline__ uint32_t smem_to_u32(const void* p) {
    uint32_t a;
    asm("{ .reg .u64 t; cvta.to.shared.u64 t, %1; cvt.u32.u64 %0, t; }" : "=r"(a) : "l"(p));
    return a;
}
#define SW128(bo) ((bo) ^ (((bo) >> 3) & 0x70))

__device__ __forceinline__ void cp_async16(uint32_t dst, const void* src) {
    asm volatile("cp.async.cg.shared.global [%0], [%1], 16;" :: "r"(dst), "l"(src) : "memory");
}
__device__ __forceinline__ void cp_commit() {
    asm volatile("cp.async.commit_group;" ::: "memory");
}
template<int N>
__device__ __forceinline__ void cp_wait() {
    asm volatile("cp.async.wait_group %0;" :: "n"(N) : "memory");
}
__device__ __forceinline__ void ldm_x4(uint32_t& r0, uint32_t& r1, uint32_t& r2, uint32_t& r3,
                                       uint32_t addr) {
    asm volatile("ldmatrix.sync.aligned.m8n8.x4.shared.b16 {%0,%1,%2,%3}, [%4];"
                 : "=r"(r0), "=r"(r1), "=r"(r2), "=r"(r3) : "r"(addr));
}
__device__ __forceinline__ void mma_fp16(float* c, const uint32_t* a, const uint32_t* b) {
    asm volatile(
        "mma.sync.aligned.m16n8k16.row.col.f32.f16.f16.f32 "
        "{%0,%1,%2,%3}, {%4,%5,%6,%7}, {%8,%9}, {%0,%1,%2,%3};"
        : "+f"(c[0]), "+f"(c[1]), "+f"(c[2]), "+f"(c[3])
        : "r"(a[0]), "r"(a[1]), "r"(a[2]), "r"(a[3]), "r"(b[0]), "r"(b[1]));
}
__device__ __forceinline__ void stcs2(float* p, float x, float y) {
    asm volatile("st.global.cs.v2.f32 [%0], {%1, %2};" :: "l"(p), "f"(x), "f"(y) : "memory");
}
__device__ __forceinline__ void stcs_h(__half* p, __half v) {
    unsigned short u = __half_as_ushort(v);
    asm volatile("st.global.cs.u16 [%0], %1;" :: "l"(p), "h"(u) : "memory");
}

// ---------------------------------------------------------------------------
// GEMM: C[M x N3] = A[M x K] @ B^T[N3 x K], pure fp16 operands, fp32 accum.
// CTA tile 128x128, BK=64, 8 warps (2m x 4n), warp tile 64x32.
// 3-stage cp.async pipeline, 32KB/stage (96KB total) -> 2 CTAs/SM.
// ---------------------------------------------------------------------------
#define OFF_A    0
#define OFF_B    16384
#define STAGE_B  32768                 // 32 KB (A 16K + B 16K)
#define GEMM_SMEM (3*STAGE_B)          // 96 KB

template<int KTOT>
__device__ __forceinline__ void load_stage(uint32_t sb, int buf, int kt,
    const __half* __restrict__ A, const __half* __restrict__ B,
    int rowBase, int colBase, int tid)
{
    const uint32_t base = sb + buf * STAGE_B;
    const int kOff = kt * 64;
    #pragma unroll
    for (int i = 0; i < 4; i++) {                 // A: 128 rows x 128B
        const int ci = tid + i * 256;             // 1024 chunks of 16B
        const int row = ci >> 3, c8 = ci & 7;
        const size_t g = (size_t)(rowBase + row) * KTOT + kOff + c8 * 8;
        const uint32_t so = SW128((uint32_t)(row * 128 + c8 * 16));
        cp_async16(base + OFF_A + so, A + g);
    }
    #pragma unroll
    for (int i = 0; i < 4; i++) {                 // B: 128 rows x 128B
        const int ci = tid + i * 256;
        const int row = ci >> 3, c8 = ci & 7;
        const size_t g = (size_t)(colBase + row) * KTOT + kOff + c8 * 8;
        const uint32_t so = SW128((uint32_t)(row * 128 + c8 * 16));
        cp_async16(base + OFF_B + so, B + g);
    }
}

__device__ __forceinline__ void compute_stage(uint32_t sb, int buf,
    int warp_m, int warp_n, int lane, float acc[4][4][4])
{
    const uint32_t base = sb + buf * STAGE_B;
    const int mrow = warp_m * 64 + (lane & 15);
    const int bg = lane >> 3, brr = lane & 7;
    #pragma unroll
    for (int k16 = 0; k16 < 4; k16++) {
        const int kc = k16 * 2 + (lane >> 4);     // 16B column (0..7) in 128B row
        uint32_t af[4][4];
        uint32_t bf[4][2];
        #pragma unroll
        for (int ma = 0; ma < 4; ma++) {
            const uint32_t so = SW128((uint32_t)((mrow + ma * 16) * 128 + kc * 16));
            ldm_x4(af[ma][0], af[ma][1], af[ma][2], af[ma][3], base + OFF_A + so);
        }
        #pragma unroll
        for (int ng = 0; ng < 2; ng++) {
            const int n = warp_n * 32 + ng * 16 + (bg >> 1) * 8 + brr;
            const uint32_t so = SW128((uint32_t)(n * 128 + (k16 * 2 + (bg & 1)) * 16));
            uint32_t r0, r1, r2, r3;
            ldm_x4(r0, r1, r2, r3, base + OFF_B + so);
            bf[ng*2][0] = r0; bf[ng*2][1] = r1; bf[ng*2+1][0] = r2; bf[ng*2+1][1] = r3;
        }
        #pragma unroll
        for (int ma = 0; ma < 4; ma++)
            #pragma unroll
            for (int na = 0; na < 4; na++) mma_fp16(acc[ma][na], af[ma], bf[na]);
    }
}

template<int KTOT>
__global__ __launch_bounds__(256, 2)
void gemm_fp16(const __half* __restrict__ A, const __half* __restrict__ B,
               float* __restrict__ C)
{
    extern __shared__ char smem[];
    const uint32_t sb = smem_to_u32(smem);
    const int tid = threadIdx.x, wid = tid >> 5, lane = tid & 31;
    const int warp_m = wid & 1, warp_n = wid >> 1;
    const int rowBase = blockIdx.y << 7;
    const int colBase = blockIdx.x << 7;
    constexpr int KT = KTOT / 64;

    float acc[4][4][4];
    #pragma unroll
    for (int i = 0; i < 4; i++)
        #pragma unroll
        for (int j = 0; j < 4; j++)
            #pragma unroll
            for (int k = 0; k < 4; k++) acc[i][j][k] = 0.f;

    load_stage<KTOT>(sb, 0, 0, A, B, rowBase, colBase, tid);
    cp_commit();
    if (KT > 1) {
        load_stage<KTOT>(sb, 1, 1, A, B, rowBase, colBase, tid);
        cp_commit();
    }

    int buf = 0;
    #pragma unroll 1
    for (int kt = 0; kt < KT; kt++) {
        if (kt + 1 < KT) cp_wait<1>(); else cp_wait<0>();
        __syncthreads();                          // stage kt ready; compute kt-1 done
        if (kt + 2 < KT) {
            int nb = buf + 2; if (nb >= 3) nb -= 3;
            load_stage<KTOT>(sb, nb, kt + 2, A, B, rowBase, colBase, tid);
            cp_commit();
        }
        compute_stage(sb, buf, warp_m, warp_n, lane, acc);
        if (++buf == 3) buf = 0;
    }

    // Epilogue: streaming fp32 stores (C is written once, read once by rec)
    const int mBase = rowBase + warp_m * 64 + (lane >> 2);
    const int nBase = colBase + warp_n * 32 + (lane & 3) * 2;
    #pragma unroll
    for (int ma = 0; ma < 4; ma++) {
        #pragma unroll
        for (int na = 0; na < 4; na++) {
            const int m = mBase + ma * 16;
            const int n = nBase + na * 8;
            stcs2(C + (size_t)m * N3_ + n,       acc[ma][na][0], acc[ma][na][1]);
            stcs2(C + (size_t)(m + 8) * N3_ + n, acc[ma][na][2], acc[ma][na][3]);
        }
    }
}

// ---------------------------------------------------------------------------
// Convert fp32 -> fp16 (elementwise, float4-vectorized)
// ---------------------------------------------------------------------------
__global__ void cvt_kernel(const float* __restrict__ src,
                           __half* __restrict__ dst, int n4)
{
    const int i = blockIdx.x * blockDim.x + threadIdx.x;
    if (i >= n4) return;
    const float4 v = reinterpret_cast<const float4*>(src)[i];
    __half2* dp = reinterpret_cast<__half2*>(dst + 4 * (size_t)i);
    dp[0] = __floats2half2_rn(v.x, v.y);
    dp[1] = __floats2half2_rn(v.z, v.w);
}

// Transpose + convert: W[K, N3] fp32 -> Wt[N3, K] fp16
__global__ void cvtT_kernel(const float* __restrict__ W,
                            __half* __restrict__ Wt, int K)
{
    const int idx = blockIdx.x * blockDim.x + threadIdx.x;
    if (idx >= K * N3_) return;
    const int k = idx / N3_, n = idx % N3_;
    Wt[(size_t)n * K + k] = __float2half_rn(W[idx]);
}

// ---------------------------------------------------------------------------
// SRU recurrence, software-pipelined (prefetch next 4-t batch before compute)
// All register arrays statically indexed (no local-mem demotion)
// ---------------------------------------------------------------------------
__device__ __forceinline__ float sigmoidf_(float z) { return 1.f / (1.f + __expf(-z)); }

__global__ __launch_bounds__(256)
void rec0_kernel(const float* __restrict__ U, const float* __restrict__ v,
                 const float* __restrict__ bias, __half* __restrict__ hOut)
{
    const int tid = blockIdx.x * blockDim.x + threadIdx.x;
    const int b = tid >> 9, h = tid & (H_ - 1);
    const float vf = v[h], vr = v[H_ + h];
    const float bf = bias[h], br = bias[H_ + h];
    float c = 0.f;
    float a0[4], a1[4], a2[4];
    #pragma unroll
    for (int i = 0; i < 4; i++) {
        const size_t base = ((size_t)i * B_ + b) * N3_ + h;
        a0[i] = __ldcs(U + base); a1[i] = __ldcs(U + base + H_); a2[i] = __ldcs(U + base + 2*H_);
    }
    for (int t0 = 0; t0 < L_; t0 += 4) {
        float n0[4] = {0,0,0,0}, n1[4] = {0,0,0,0}, n2[4] = {0,0,0,0};
        if (t0 + 4 < L_) {
            #pragma unroll
            for (int i = 0; i < 4; i++) {
                const size_t base = ((size_t)(t0 + 4 + i) * B_ + b) * N3_ + h;
                n0[i] = __ldcs(U + base); n1[i] = __ldcs(U + base + H_); n2[i] = __ldcs(U + base + 2*H_);
            }
        }
        #pragma unroll
        for (int i = 0; i < 4; i++) {
            const float f = sigmoidf_(a1[i] + vf * c + bf);
            const float r = sigmoidf_(a2[i] + vr * c + br);
            c = f * c + (1.f - f) * a0[i];
            const float hv = r * c;
            const size_t o = ((size_t)(t0 + i) * B_ + b) * H_ + h;
            stcs_h(hOut + o, __float2half_rn(hv));
        }
        #pragma unroll
        for (int i = 0; i < 4; i++) { a0[i] = n0[i]; a1[i] = n1[i]; a2[i] = n2[i]; }
    }
}

__global__ __launch_bounds__(256)
void rec1_kernel(const float* __restrict__ U, const float* __restrict__ v,
                 const float* __restrict__ bias, float* __restrict__ hout)
{
    const int tid = blockIdx.x * blockDim.x + threadIdx.x;
    const int b = tid >> 9, h = tid & (H_ - 1);
    const float vf = v[h], vr = v[H_ + h];
    const float bf = bias[h], br = bias[H_ + h];
    float c = 0.f, hlast = 0.f;
    float a0[4], a1[4], a2[4];
    #pragma unroll
    for (int i = 0; i < 4; i++) {
        const size_t base = ((size_t)i * B_ + b) * N3_ + h;
        a0[i] = __ldcs(U + base); a1[i] = __ldcs(U + base + H_); a2[i] = __ldcs(U + base + 2*H_);
    }
    for (int t0 = 0; t0 < L_; t0 += 4) {
        float n0[4] = {0,0,0,0}, n1[4] = {0,0,0,0}, n2[4] = {0,0,0,0};
        if (t0 + 4 < L_) {
            #pragma unroll
            for (int i = 0; i < 4; i++) {
                const size_t base = ((size_t)(t0 + 4 + i) * B_ + b) * N3_ + h;
                n0[i] = __ldcs(U + base); n1[i] = __ldcs(U + base + H_); n2[i] = __ldcs(U + base + 2*H_);
            }
        }
        #pragma unroll
        for (int i = 0; i < 4; i++) {
            const float f = sigmoidf_(a1[i] + vf * c + bf);
            const float r = sigmoidf_(a2[i] + vr * c + br);
            c = f * c + (1.f - f) * a0[i];
            hlast = r * c;
        }
        #pragma unroll
        for (int i = 0; i < 4; i++) { a0[i] = n0[i]; a1[i] = n1[i]; a2[i] = n2[i]; }
    }
    hout[b * H_ + h] = hlast;
}

// ---------------------------------------------------------------------------
// Final FC: out[b,o] = h2[b,:] . fc_w[o,:] + fc_b[o]
// ---------------------------------------------------------------------------
__global__ void fc_kernel(const float* __restrict__ h2, const float* __restrict__ w,
                          const float* __restrict__ bias, float* __restrict__ out)
{
    const int gtid = blockIdx.x * blockDim.x + threadIdx.x;
    const int warp = gtid >> 5, lane = gtid & 31;
    if (warp >= B_) return;
    #pragma unroll
    for (int o = 0; o < OUT_; o++) {
        float s = 0.f;
        for (int h = lane; h < H_; h += 32) s += h2[warp * H_ + h] * w[o * H_ + h];
        #pragma unroll
        for (int off = 16; off > 0; off >>= 1) s += __shfl_down_sync(0xffffffffu, s, off);
        if (lane == 0) out[warp * OUT_ + o] = s + bias[o];
    }
}

// ---------------------------------------------------------------------------
extern "C" void kernel_launch(void* const* d_in, const int* in_sizes, int n_in,
                              void* d_out, int out_size)
{
    const float* x   = (const float*)d_in[0];
    const float* W0  = (const float*)d_in[1];
    const float* v0  = (const float*)d_in[2];
    const float* b0  = (const float*)d_in[3];
    const float* W1  = (const float*)d_in[4];
    const float* v1  = (const float*)d_in[5];
    const float* b1  = (const float*)d_in[6];
    const float* fcw = (const float*)d_in[7];
    const float* fcb = (const float*)d_in[8];
    float* out = (float*)d_out;

    float *pU, *pH2;
    __half *pA, *pB;
    cudaGetSymbolAddress((void**)&pU,  g_U);
    cudaGetSymbolAddress((void**)&pA,  g_A16);
    cudaGetSymbolAddress((void**)&pB,  g_Bt);
    cudaGetSymbolAddress((void**)&pH2, g_h2);

    cudaFuncSetAttribute(gemm_fp16<128>, cudaFuncAttributeMaxDynamicSharedMemorySize, GEMM_SMEM);
    cudaFuncSetAttribute(gemm_fp16<512>, cudaFuncAttributeMaxDynamicSharedMemorySize, GEMM_SMEM);

    const dim3 gemmGrid(N3_ / 128, M_ / 128);   // (12, 512) — n fast for A L2 reuse

    // ---- Layer 0 ----
    cvt_kernel<<<(M_ * D_ / 4 + 255) / 256, 256>>>(x, pA, M_ * D_ / 4);
    cvtT_kernel<<<(D_ * N3_ + 255) / 256, 256>>>(W0, pB, D_);
    gemm_fp16<128><<<gemmGrid, 256, GEMM_SMEM>>>(pA, pB, pU);
    rec0_kernel<<<(B_ * H_) / 256, 256>>>(pU, v0, b0, pA);   // h1 written as fp16

    // ---- Layer 1 ----
    cvtT_kernel<<<(H_ * N3_ + 255) / 256, 256>>>(W1, pB, H_);
    gemm_fp16<512><<<gemmGrid, 256, GEMM_SMEM>>>(pA, pB, pU);
    rec1_kernel<<<(B_ * H_) / 256, 256>>>(pU, v1, b1, pH2);

    // ---- Head ----
    fc_kernel<<<(B_ * 32 + 255) / 256, 256>>>(pH2, fcw, fcb, out);
}

// round 15
// speedup vs baseline: 2.3979x; 1.0527x over previous
#include <cuda_runtime.h>
#include <cuda_fp16.h>
#include <cstdint>

#define L_   512
#define B_   128
#define D_   128
#define H_   512
#define OUT_ 5
#define M_   (L_*B_)     // 65536 rows
#define N3_  (3*H_)      // 1536 cols

// ---------------------------------------------------------------------------
// Static device scratch (no cudaMalloc allowed)
// ---------------------------------------------------------------------------
__device__ float  g_U  [(size_t)M_ * N3_];      // 402 MB
__device__ __half g_A16[(size_t)M_ * H_];       // 64 MB: x (M x D) then h1 (M x H)
__device__ __half g_Bt [(size_t)N3_ * H_];      // 1.5 MB: W^T fp16
__device__ float  g_h2 [B_ * H_];

// ---------------------------------------------------------------------------
// Helpers (base-ISA only: ldmatrix / mma.sync / cp.async — no 'a' features)
// ---------------------------------------------------------------------------
__device__ __forceinline__ uint32_t smem_to_u32(const void* p) {
    uint32_t a;
    asm("{ .reg .u64 t; cvta.to.shared.u64 t, %1; cvt.u32.u64 %0, t; }" : "=r"(a) : "l"(p));
    return a;
}
#define SW128(bo) ((bo) ^ (((bo) >> 3) & 0x70))

__device__ __forceinline__ void cp_async16(uint32_t dst, const void* src) {
    asm volatile("cp.async.cg.shared.global [%0], [%1], 16;" :: "r"(dst), "l"(src) : "memory");
}
__device__ __forceinline__ void cp_commit() {
    asm volatile("cp.async.commit_group;" ::: "memory");
}
template<int N>
__device__ __forceinline__ void cp_wait() {
    asm volatile("cp.async.wait_group %0;" :: "n"(N) : "memory");
}
__device__ __forceinline__ void ldm_x4(uint32_t& r0, uint32_t& r1, uint32_t& r2, uint32_t& r3,
                                       uint32_t addr) {
    asm volatile("ldmatrix.sync.aligned.m8n8.x4.shared.b16 {%0,%1,%2,%3}, [%4];"
                 : "=r"(r0), "=r"(r1), "=r"(r2), "=r"(r3) : "r"(addr));
}
__device__ __forceinline__ void mma_fp16(float* c, const uint32_t* a, const uint32_t* b) {
    asm volatile(
        "mma.sync.aligned.m16n8k16.row.col.f32.f16.f16.f32 "
        "{%0,%1,%2,%3}, {%4,%5,%6,%7}, {%8,%9}, {%0,%1,%2,%3};"
        : "+f"(c[0]), "+f"(c[1]), "+f"(c[2]), "+f"(c[3])
        : "r"(a[0]), "r"(a[1]), "r"(a[2]), "r"(a[3]), "r"(b[0]), "r"(b[1]));
}
__device__ __forceinline__ void stcs2(float* p, float x, float y) {
    asm volatile("st.global.cs.v2.f32 [%0], {%1, %2};" :: "l"(p), "f"(x), "f"(y) : "memory");
}
__device__ __forceinline__ void stcs_h(__half* p, __half v) {
    unsigned short u = __half_as_ushort(v);
    asm volatile("st.global.cs.u16 [%0], %1;" :: "l"(p), "h"(u) : "memory");
}

// ---------------------------------------------------------------------------
// GEMM: C[M x N3] = A[M x K] @ B^T[N3 x K], fp16 operands, fp32 accum.
// CTA tile 128x128, BK=64, 4 warps (2m x 2n), warp tile 64x64.
// Per k16/warp: 8 ldsm.x4 (4KB) feed 32 HMMAs -> crossbar/tensor balanced.
// 3-stage cp.async pipeline, 32KB/stage (96KB) -> 2 CTAs/SM.
// ---------------------------------------------------------------------------
#define OFF_A    0
#define OFF_B    16384
#define STAGE_B  32768                 // 32 KB (A 16K + B 16K)
#define GEMM_SMEM (3*STAGE_B)          // 96 KB
#define GTHREADS 128

template<int KTOT>
__device__ __forceinline__ void load_stage(uint32_t sb, int buf, int kt,
    const __half* __restrict__ A, const __half* __restrict__ B,
    int rowBase, int colBase, int tid)
{
    const uint32_t base = sb + buf * STAGE_B;
    const int kOff = kt * 64;
    #pragma unroll
    for (int i = 0; i < 8; i++) {                 // A: 128 rows x 128B (1024 chunks)
        const int ci = tid + i * GTHREADS;
        const int row = ci >> 3, c8 = ci & 7;
        const size_t g = (size_t)(rowBase + row) * KTOT + kOff + c8 * 8;
        const uint32_t so = SW128((uint32_t)(row * 128 + c8 * 16));
        cp_async16(base + OFF_A + so, A + g);
    }
    #pragma unroll
    for (int i = 0; i < 8; i++) {                 // B: 128 rows x 128B
        const int ci = tid + i * GTHREADS;
        const int row = ci >> 3, c8 = ci & 7;
        const size_t g = (size_t)(colBase + row) * KTOT + kOff + c8 * 8;
        const uint32_t so = SW128((uint32_t)(row * 128 + c8 * 16));
        cp_async16(base + OFF_B + so, B + g);
    }
}

__device__ __forceinline__ void compute_stage(uint32_t sb, int buf,
    int warp_m, int warp_n, int lane, float acc[4][8][4])
{
    const uint32_t base = sb + buf * STAGE_B;
    const int mrow = warp_m * 64 + (lane & 15);
    const int bg = lane >> 3, brr = lane & 7;
    #pragma unroll
    for (int k16 = 0; k16 < 4; k16++) {
        const int kc = k16 * 2 + (lane >> 4);     // 16B column (0..7) in 128B row
        uint32_t af[4][4];
        uint32_t bf[8][2];
        #pragma unroll
        for (int ma = 0; ma < 4; ma++) {
            const uint32_t so = SW128((uint32_t)((mrow + ma * 16) * 128 + kc * 16));
            ldm_x4(af[ma][0], af[ma][1], af[ma][2], af[ma][3], base + OFF_A + so);
        }
        #pragma unroll
        for (int ng = 0; ng < 4; ng++) {
            const int n = warp_n * 64 + ng * 16 + (bg >> 1) * 8 + brr;
            const uint32_t so = SW128((uint32_t)(n * 128 + (k16 * 2 + (bg & 1)) * 16));
            uint32_t r0, r1, r2, r3;
            ldm_x4(r0, r1, r2, r3, base + OFF_B + so);
            bf[ng*2][0] = r0; bf[ng*2][1] = r1; bf[ng*2+1][0] = r2; bf[ng*2+1][1] = r3;
        }
        #pragma unroll
        for (int ma = 0; ma < 4; ma++)
            #pragma unroll
            for (int na = 0; na < 8; na++) mma_fp16(acc[ma][na], af[ma], bf[na]);
    }
}

template<int KTOT>
__global__ __launch_bounds__(GTHREADS, 2)
void gemm_fp16(const __half* __restrict__ A, const __half* __restrict__ B,
               float* __restrict__ C)
{
    extern __shared__ char smem[];
    const uint32_t sb = smem_to_u32(smem);
    const int tid = threadIdx.x, wid = tid >> 5, lane = tid & 31;
    const int warp_m = wid & 1, warp_n = wid >> 1;
    const int rowBase = blockIdx.y << 7;
    const int colBase = blockIdx.x << 7;
    constexpr int KT = KTOT / 64;

    float acc[4][8][4];
    #pragma unroll
    for (int i = 0; i < 4; i++)
        #pragma unroll
        for (int j = 0; j < 8; j++)
            #pragma unroll
            for (int k = 0; k < 4; k++) acc[i][j][k] = 0.f;

    load_stage<KTOT>(sb, 0, 0, A, B, rowBase, colBase, tid);
    cp_commit();
    if (KT > 1) {
        load_stage<KTOT>(sb, 1, 1, A, B, rowBase, colBase, tid);
        cp_commit();
    }

    int buf = 0;
    #pragma unroll 1
    for (int kt = 0; kt < KT; kt++) {
        if (kt + 1 < KT) cp_wait<1>(); else cp_wait<0>();
        __syncthreads();                          // stage kt ready; compute kt-1 done
        if (kt + 2 < KT) {
            int nb = buf + 2; if (nb >= 3) nb -= 3;
            load_stage<KTOT>(sb, nb, kt + 2, A, B, rowBase, colBase, tid);
            cp_commit();
        }
        compute_stage(sb, buf, warp_m, warp_n, lane, acc);
        if (++buf == 3) buf = 0;
    }

    // Epilogue: streaming fp32 stores (C written once, read once by rec)
    const int mBase = rowBase + warp_m * 64 + (lane >> 2);
    const int nBase = colBase + warp_n * 64 + (lane & 3) * 2;
    #pragma unroll
    for (int ma = 0; ma < 4; ma++) {
        #pragma unroll
        for (int na = 0; na < 8; na++) {
            const int m = mBase + ma * 16;
            const int n = nBase + na * 8;
            stcs2(C + (size_t)m * N3_ + n,       acc[ma][na][0], acc[ma][na][1]);
            stcs2(C + (size_t)(m + 8) * N3_ + n, acc[ma][na][2], acc[ma][na][3]);
        }
    }
}

// ---------------------------------------------------------------------------
// Convert fp32 -> fp16 (elementwise, float4-vectorized)
// ---------------------------------------------------------------------------
__global__ void cvt_kernel(const float* __restrict__ src,
                           __half* __restrict__ dst, int n4)
{
    const int i = blockIdx.x * blockDim.x + threadIdx.x;
    if (i >= n4) return;
    const float4 v = reinterpret_cast<const float4*>(src)[i];
    __half2* dp = reinterpret_cast<__half2*>(dst + 4 * (size_t)i);
    dp[0] = __floats2half2_rn(v.x, v.y);
    dp[1] = __floats2half2_rn(v.z, v.w);
}

// Transpose + convert: W[K, N3] fp32 -> Wt[N3, K] fp16
__global__ void cvtT_kernel(const float* __restrict__ W,
                            __half* __restrict__ Wt, int K)
{
    const int idx = blockIdx.x * blockDim.x + threadIdx.x;
    if (idx >= K * N3_) return;
    const int k = idx / N3_, n = idx % N3_;
    Wt[(size_t)n * K + k] = __float2half_rn(W[idx]);
}

// ---------------------------------------------------------------------------
// SRU recurrence. 4 statically-indexed register windows (distance-3 prefetch),
// loop unrolled x4 so every buffer index is compile-time (no local-mem demotion)
// ---------------------------------------------------------------------------
__device__ __forceinline__ float sigmoidf_(float z) { return 1.f / (1.f + __expf(-z)); }

__device__ __forceinline__ void rec_ld(const float* __restrict__ U, int b, int h, int t0,
                                       float u0[4], float u1[4], float u2[4])
{
    #pragma unroll
    for (int i = 0; i < 4; i++) {
        const size_t base = ((size_t)(t0 + i) * B_ + b) * N3_ + h;
        u0[i] = __ldcs(U + base);
        u1[i] = __ldcs(U + base + H_);
        u2[i] = __ldcs(U + base + 2*H_);
    }
}

__device__ __forceinline__ void rec0_win(const float u0[4], const float u1[4], const float u2[4],
    float& c, int t0, int b, int h, __half* __restrict__ hOut,
    float vf, float vr, float bfv, float brv)
{
    #pragma unroll
    for (int i = 0; i < 4; i++) {
        const float f = sigmoidf_(u1[i] + vf * c + bfv);
        const float r = sigmoidf_(u2[i] + vr * c + brv);
        c = f * c + (1.f - f) * u0[i];
        stcs_h(hOut + ((size_t)(t0 + i) * B_ + b) * H_ + h, __float2half_rn(r * c));
    }
}

__device__ __forceinline__ void rec1_win(const float u0[4], const float u1[4], const float u2[4],
    float& c, float& hlast, float vf, float vr, float bfv, float brv)
{
    #pragma unroll
    for (int i = 0; i < 4; i++) {
        const float f = sigmoidf_(u1[i] + vf * c + bfv);
        const float r = sigmoidf_(u2[i] + vr * c + brv);
        c = f * c + (1.f - f) * u0[i];
        hlast = r * c;
    }
}

__global__ __launch_bounds__(256)
void rec0_kernel(const float* __restrict__ U, const float* __restrict__ v,
                 const float* __restrict__ bias, __half* __restrict__ hOut)
{
    const int tid = blockIdx.x * blockDim.x + threadIdx.x;
    const int b = tid >> 9, h = tid & (H_ - 1);
    const float vf = v[h], vr = v[H_ + h];
    const float bfv = bias[h], brv = bias[H_ + h];
    float c = 0.f;
    float p0[4], p1[4], p2[4], q0[4], q1[4], q2[4];
    float w0[4], w1[4], w2[4], s0[4], s1[4], s2[4];
    rec_ld(U, b, h, 0,  p0, p1, p2);
    rec_ld(U, b, h, 4,  q0, q1, q2);
    rec_ld(U, b, h, 8,  w0, w1, w2);
    rec_ld(U, b, h, 12, s0, s1, s2);
    #pragma unroll 1
    for (int t0 = 0; t0 < L_; t0 += 16) {
        rec0_win(p0, p1, p2, c, t0,      b, h, hOut, vf, vr, bfv, brv);
        if (t0 + 16 < L_) rec_ld(U, b, h, t0 + 16, p0, p1, p2);
        rec0_win(q0, q1, q2, c, t0 + 4,  b, h, hOut, vf, vr, bfv, brv);
        if (t0 + 20 < L_) rec_ld(U, b, h, t0 + 20, q0, q1, q2);
        rec0_win(w0, w1, w2, c, t0 + 8,  b, h, hOut, vf, vr, bfv, brv);
        if (t0 + 24 < L_) rec_ld(U, b, h, t0 + 24, w0, w1, w2);
        rec0_win(s0, s1, s2, c, t0 + 12, b, h, hOut, vf, vr, bfv, brv);
        if (t0 + 28 < L_) rec_ld(U, b, h, t0 + 28, s0, s1, s2);
    }
}

__global__ __launch_bounds__(256)
void rec1_kernel(const float* __restrict__ U, const float* __restrict__ v,
                 const float* __restrict__ bias, float* __restrict__ hout)
{
    const int tid = blockIdx.x * blockDim.x + threadIdx.x;
    const int b = tid >> 9, h = tid & (H_ - 1);
    const float vf = v[h], vr = v[H_ + h];
    const float bfv = bias[h], brv = bias[H_ + h];
    float c = 0.f, hlast = 0.f;
    float p0[4], p1[4], p2[4], q0[4], q1[4], q2[4];
    float w0[4], w1[4], w2[4], s0[4], s1[4], s2[4];
    rec_ld(U, b, h, 0,  p0, p1, p2);
    rec_ld(U, b, h, 4,  q0, q1, q2);
    rec_ld(U, b, h, 8,  w0, w1, w2);
    rec_ld(U, b, h, 12, s0, s1, s2);
    #pragma unroll 1
    for (int t0 = 0; t0 < L_; t0 += 16) {
        rec1_win(p0, p1, p2, c, hlast, vf, vr, bfv, brv);
        if (t0 + 16 < L_) rec_ld(U, b, h, t0 + 16, p0, p1, p2);
        rec1_win(q0, q1, q2, c, hlast, vf, vr, bfv, brv);
        if (t0 + 20 < L_) rec_ld(U, b, h, t0 + 20, q0, q1, q2);
        rec1_win(w0, w1, w2, c, hlast, vf, vr, bfv, brv);
        if (t0 + 24 < L_) rec_ld(U, b, h, t0 + 24, w0, w1, w2);
        rec1_win(s0, s1, s2, c, hlast, vf, vr, bfv, brv);
        if (t0 + 28 < L_) rec_ld(U, b, h, t0 + 28, s0, s1, s2);
    }
    hout[b * H_ + h] = hlast;
}

// ---------------------------------------------------------------------------
// Final FC: out[b,o] = h2[b,:] . fc_w[o,:] + fc_b[o]
// ---------------------------------------------------------------------------
__global__ void fc_kernel(const float* __restrict__ h2, const float* __restrict__ w,
                          const float* __restrict__ bias, float* __restrict__ out)
{
    const int gtid = blockIdx.x * blockDim.x + threadIdx.x;
    const int warp = gtid >> 5, lane = gtid & 31;
    if (warp >= B_) return;
    #pragma unroll
    for (int o = 0; o < OUT_; o++) {
        float s = 0.f;
        for (int h = lane; h < H_; h += 32) s += h2[warp * H_ + h] * w[o * H_ + h];
        #pragma unroll
        for (int off = 16; off > 0; off >>= 1) s += __shfl_down_sync(0xffffffffu, s, off);
        if (lane == 0) out[warp * OUT_ + o] = s + bias[o];
    }
}

// ---------------------------------------------------------------------------
extern "C" void kernel_launch(void* const* d_in, const int* in_sizes, int n_in,
                              void* d_out, int out_size)
{
    const float* x   = (const float*)d_in[0];
    const float* W0  = (const float*)d_in[1];
    const float* v0  = (const float*)d_in[2];
    const float* b0  = (const float*)d_in[3];
    const float* W1  = (const float*)d_in[4];
    const float* v1  = (const float*)d_in[5];
    const float* b1  = (const float*)d_in[6];
    const float* fcw = (const float*)d_in[7];
    const float* fcb = (const float*)d_in[8];
    float* out = (float*)d_out;

    float *pU, *pH2;
    __half *pA, *pB;
    cudaGetSymbolAddress((void**)&pU,  g_U);
    cudaGetSymbolAddress((void**)&pA,  g_A16);
    cudaGetSymbolAddress((void**)&pB,  g_Bt);
    cudaGetSymbolAddress((void**)&pH2, g_h2);

    cudaFuncSetAttribute(gemm_fp16<128>, cudaFuncAttributeMaxDynamicSharedMemorySize, GEMM_SMEM);
    cudaFuncSetAttribute(gemm_fp16<512>, cudaFuncAttributeMaxDynamicSharedMemorySize, GEMM_SMEM);

    const dim3 gemmGrid(N3_ / 128, M_ / 128);   // (12, 512) — n fast for A L2 reuse

    // ---- Layer 0 ----
    cvt_kernel<<<(M_ * D_ / 4 + 255) / 256, 256>>>(x, pA, M_ * D_ / 4);
    cvtT_kernel<<<(D_ * N3_ + 255) / 256, 256>>>(W0, pB, D_);
    gemm_fp16<128><<<gemmGrid, GTHREADS, GEMM_SMEM>>>(pA, pB, pU);
    rec0_kernel<<<(B_ * H_) / 256, 256>>>(pU, v0, b0, pA);   // h1 written as fp16

    // ---- Layer 1 ----
    cvtT_kernel<<<(H_ * N3_ + 255) / 256, 256>>>(W1, pB, H_);
    gemm_fp16<512><<<gemmGrid, GTHREADS, GEMM_SMEM>>>(pA, pB, pU);
    rec1_kernel<<<(B_ * H_) / 256, 256>>>(pU, v1, b1, pH2);

    // ---- Head ----
    fc_kernel<<<(B_ * 32 + 255) / 256, 256>>>(pH2, fcw, fcb, out);
}